// round 5
// baseline (speedup 1.0000x reference)
#include <cuda_runtime.h>
#include <cuda_bf16.h>
#include <cstdint>

#define NN 100000
#define NE 800000
// dims: 128 -> 64 -> 64 -> 7

// ---------------- scratch (device globals; no allocation allowed) ----------
__device__ __align__(256) float g_h[NN * 64];   // GEMM output of current layer
__device__ __align__(256) float g_a[NN * 64];   // aggregated output / next input
__device__ float g_dinv[NN];
__device__ int   g_deg[NN];
__device__ int   g_cursor[NN];
__device__ int   g_rowptr[NN + 1];
__device__ int   g_src[NE];
__device__ int   g_dst[NE];
__device__ int   g_csr_src[NE];
__device__ float g_csr_coef[NE];
__device__ int   g_is64;

// ---------------- helpers --------------------------------------------------
__device__ __forceinline__ void ffma2(unsigned long long& acc,
                                      unsigned long long a,
                                      unsigned long long b) {
    asm("fma.rn.f32x2 %0, %1, %2, %0;" : "+l"(acc) : "l"(a), "l"(b));
}

__device__ __forceinline__ unsigned long long dup2(float v) {
    unsigned int u = __float_as_uint(v);
    return ((unsigned long long)u << 32) | (unsigned long long)u;
}

__device__ __forceinline__ float lo32(unsigned long long v) {
    return __uint_as_float((unsigned int)(v & 0xffffffffull));
}
__device__ __forceinline__ float hi32(unsigned long long v) {
    return __uint_as_float((unsigned int)(v >> 32));
}

// ---------------- edge dtype detection / normalization ---------------------
__global__ void detect_kernel(const void* edges) {
    const long long* p = (const long long*)edges;
    int i = threadIdx.x;
    long long v = p[i];                 // 1024 int64 reads = first 2048 int32s, in-bounds
    int ok = (v >= 0 && v < NN);
    int all = __syncthreads_and(ok);
    if (i == 0) g_is64 = all;           // all plausible as int64 => really int64
}

__global__ void zero_kernel() {
    int i = blockIdx.x * blockDim.x + threadIdx.x;
    if (i < NN) { g_deg[i] = 0; g_cursor[i] = 0; }
}

__global__ void convert_edges_kernel(const void* edges) {
    int e = blockIdx.x * blockDim.x + threadIdx.x;
    if (e >= NE) return;
    int s, d;
    if (g_is64) {
        const long long* p = (const long long*)edges;
        s = (int)p[e];
        d = (int)p[NE + e];
    } else {
        const int* p = (const int*)edges;
        s = p[e];
        d = p[NE + e];
    }
    g_src[e] = s;
    g_dst[e] = d;
    atomicAdd(&g_deg[d], 1);
}

__global__ void dinv_kernel() {
    int i = blockIdx.x * blockDim.x + threadIdx.x;
    if (i < NN) g_dinv[i] = rsqrtf((float)g_deg[i] + 1.0f);
}

// Single-block exclusive scan of g_deg -> g_rowptr (1024 threads, ~98 elems each)
__global__ void __launch_bounds__(1024) scan_kernel() {
    __shared__ int s[1024];
    const int CH = (NN + 1023) / 1024;          // 98
    int t = threadIdx.x;
    int base = t * CH;
    int sum = 0;
    for (int j = 0; j < CH; j++) {
        int i = base + j;
        if (i < NN) sum += g_deg[i];
    }
    s[t] = sum;
    __syncthreads();
    // Hillis-Steele inclusive scan
    for (int off = 1; off < 1024; off <<= 1) {
        int v = (t >= off) ? s[t - off] : 0;
        __syncthreads();
        s[t] += v;
        __syncthreads();
    }
    int run = (t == 0) ? 0 : s[t - 1];          // exclusive prefix for this chunk
    for (int j = 0; j < CH; j++) {
        int i = base + j;
        if (i < NN) { g_rowptr[i] = run; run += g_deg[i]; }
    }
    if (t == 0) g_rowptr[NN] = NE;
}

// Bucket edges by destination; compute normalization coefficient in place.
__global__ void csr_fill_kernel() {
    int e = blockIdx.x * blockDim.x + threadIdx.x;
    if (e >= NE) return;
    int s = g_src[e];
    int d = g_dst[e];
    int pos = atomicAdd(&g_cursor[d], 1);
    int slot = g_rowptr[d] + pos;
    g_csr_src[slot] = s;
    g_csr_coef[slot] = g_dinv[s] * g_dinv[d];
}

// ---------------- GEMM: [nrows,FIN] @ [FIN,64] -> [nrows,64] ---------------
// 64x64 output tile per 256-thread block, K chunked by 32.
// Inner loop uses packed fma.rn.f32x2: X tile stored duplicated ({v,v} u64)
// so the broadcast A operand is a single LDS.64; B column pairs come directly
// from the W tile bytes as ulonglong2 (one LDS.128).
// RELU applies relu to input X at load time (fused previous-layer activation).
template <int FIN, bool RELU>
__global__ void __launch_bounds__(256) gemm64_kernel(
    const float* __restrict__ X, const float* __restrict__ W,
    float* __restrict__ H, int nrows)
{
    constexpr int KC = 32;
    __shared__ unsigned long long sxp[64 * KC];   // 16KB: duplicated X tile
    __shared__ float4 sw4[KC * 16];               // 8KB : W tile (KC x 64)
    const ulonglong2* swp = reinterpret_cast<const ulonglong2*>(sw4);

    const int t  = threadIdx.x;
    const int tr = t >> 4;          // 0..15 -> rows tr*4..tr*4+3
    const int tc = t & 15;          // 0..15 -> cols tc*4..tc*4+3
    const int row0 = blockIdx.x * 64;

    unsigned long long acc[4][2];
    #pragma unroll
    for (int I = 0; I < 4; I++) { acc[I][0] = 0ull; acc[I][1] = 0ull; }

    for (int kc = 0; kc < FIN; kc += KC) {
        // load X tile: 64 rows x 8 float4 (coalesced, guarded), duplicated store
        #pragma unroll
        for (int idx = t; idx < 64 * 8; idx += 256) {
            int r = idx >> 3, kq = idx & 7;
            float4 v = make_float4(0.f, 0.f, 0.f, 0.f);
            int row = row0 + r;
            if (row < nrows)
                v = ((const float4*)X)[row * (FIN / 4) + (kc >> 2) + kq];
            if (RELU) {
                v.x = fmaxf(v.x, 0.f); v.y = fmaxf(v.y, 0.f);
                v.z = fmaxf(v.z, 0.f); v.w = fmaxf(v.w, 0.f);
            }
            unsigned long long* dst = &sxp[r * KC + kq * 4];
            dst[0] = dup2(v.x); dst[1] = dup2(v.y);
            dst[2] = dup2(v.z); dst[3] = dup2(v.w);
        }
        // load W tile: KC x 16 float4 (coalesced)
        #pragma unroll
        for (int idx = t; idx < KC * 16; idx += 256) {
            sw4[idx] = ((const float4*)W)[(kc + (idx >> 4)) * 16 + (idx & 15)];
        }
        __syncthreads();

        #pragma unroll
        for (int k = 0; k < KC; k++) {
            ulonglong2 b = swp[k * 16 + tc];          // cols tc*4..tc*4+3
            #pragma unroll
            for (int I = 0; I < 4; I++) {
                unsigned long long a = sxp[(tr * 4 + I) * KC + k];  // {v,v}
                ffma2(acc[I][0], a, b.x);
                ffma2(acc[I][1], a, b.y);
            }
        }
        __syncthreads();
    }

    #pragma unroll
    for (int I = 0; I < 4; I++) {
        int row = row0 + tr * 4 + I;
        if (row < nrows) {
            float4 o;
            o.x = lo32(acc[I][0]); o.y = hi32(acc[I][0]);
            o.z = lo32(acc[I][1]); o.w = hi32(acc[I][1]);
            ((float4*)H)[row * 16 + tc] = o;
        }
    }
}

// ---------------- GEMM: [nrows,64] @ [64,7] -> [nrows,7] -------------------
// Applies relu to X at load (input is layer-2 pre-relu aggregation output).
__global__ void __launch_bounds__(256) gemm7_kernel(
    const float* __restrict__ X, const float* __restrict__ W,
    float* __restrict__ H, int nrows)
{
    __shared__ float sx[64 * 65];
    __shared__ float sw[64 * 7];
    int t = threadIdx.x;
    int row0 = blockIdx.x * 64;

    for (int idx = t; idx < 64 * 16; idx += 256) {
        int r = idx >> 4, kq = idx & 15;
        float4 v = make_float4(0.f, 0.f, 0.f, 0.f);
        int row = row0 + r;
        if (row < nrows) v = ((const float4*)X)[row * 16 + kq];
        float* dst = &sx[r * 65 + kq * 4];
        dst[0] = fmaxf(v.x, 0.f); dst[1] = fmaxf(v.y, 0.f);
        dst[2] = fmaxf(v.z, 0.f); dst[3] = fmaxf(v.w, 0.f);
    }
    // FIX (round 5): 64*7 = 448 > 256 threads; previous `if (t < 448)` left
    // sw[256..447] uninitialized -> garbage in W3 rows k>=36 (rel_err 0.89).
    for (int idx = t; idx < 64 * 7; idx += 256) sw[idx] = W[idx];
    __syncthreads();

    for (int o = t; o < 64 * 7; o += 256) {
        int r = o / 7, c = o % 7;
        float acc = 0.f;
        #pragma unroll 8
        for (int k = 0; k < 64; k++)
            acc += sx[r * 65 + k] * sw[k * 7 + c];
        int row = row0 + r;
        if (row < nrows) H[row * 7 + c] = acc;
    }
}

// ---------------- aggregation (CSR gather), F = 64 -------------------------
// out[i] = sum_{e in in(i)} coef[e]*h[src[e]] + h[i]*dinv[i]^2 + bias
// 16 threads per node (one float4 feature chunk each).
__global__ void __launch_bounds__(256) gather64_kernel(
    const float* __restrict__ H, const float* __restrict__ B,
    float* __restrict__ OUT)
{
    int gid = blockIdx.x * blockDim.x + threadIdx.x;   // NN*16 threads
    if (gid >= NN * 16) return;
    int i = gid >> 4, q = gid & 15;
    int beg = g_rowptr[i];
    int end = g_rowptr[i + 1];
    float s = g_dinv[i];
    float c = s * s;
    float4 v = ((const float4*)H)[i * 16 + q];
    float4 b = ((const float4*)B)[q];
    float4 acc;
    acc.x = v.x * c + b.x; acc.y = v.y * c + b.y;
    acc.z = v.z * c + b.z; acc.w = v.w * c + b.w;
    for (int e = beg; e < end; e++) {
        int   src = g_csr_src[e];          // broadcast across the 16 lanes
        float co  = g_csr_coef[e];
        float4 hv = ((const float4*)H)[src * 16 + q];
        acc.x += co * hv.x; acc.y += co * hv.y;
        acc.z += co * hv.z; acc.w += co * hv.w;
    }
    ((float4*)OUT)[i * 16 + q] = acc;
}

// ---------------- aggregation (CSR gather), F = 7 --------------------------
__global__ void __launch_bounds__(256) gather7_kernel(
    const float* __restrict__ H, const float* __restrict__ B,
    float* __restrict__ OUT)
{
    int gid = blockIdx.x * blockDim.x + threadIdx.x;   // NN*8 threads
    if (gid >= NN * 8) return;
    int i = gid >> 3, c = gid & 7;
    if (c >= 7) return;
    int beg = g_rowptr[i];
    int end = g_rowptr[i + 1];
    float s = g_dinv[i];
    float acc = H[i * 7 + c] * (s * s) + B[c];
    for (int e = beg; e < end; e++) {
        int   src = g_csr_src[e];
        float co  = g_csr_coef[e];
        acc += co * H[src * 7 + c];
    }
    OUT[i * 7 + c] = acc;
}

// ---------------- launch ---------------------------------------------------
extern "C" void kernel_launch(void* const* d_in, const int* in_sizes, int n_in,
                              void* d_out, int out_size)
{
    const float* x     = (const float*)d_in[0];
    const void*  edges = d_in[1];
    const float* W1    = (const float*)d_in[2];
    const float* b1    = (const float*)d_in[3];
    const float* W2    = (const float*)d_in[4];
    const float* b2    = (const float*)d_in[5];
    const float* W3    = (const float*)d_in[6];
    const float* b3    = (const float*)d_in[7];
    float* out = (float*)d_out;

    float* h = nullptr; float* a = nullptr;
    cudaGetSymbolAddress((void**)&h, g_h);
    cudaGetSymbolAddress((void**)&a, g_a);

    const int T = 256;
    const int gN   = (NN + T - 1) / T;          // 391
    const int gE   = (NE + T - 1) / T;          // 3125
    const int gN16 = (NN * 16 + T - 1) / T;     // 6250
    const int gN8  = (NN * 8 + T - 1) / T;      // 3125
    const int gRow = (NN + 63) / 64;            // 1563

    // preprocessing: edge dtype, degree, dinv, rowptr scan, CSR fill (+coef)
    detect_kernel<<<1, 1024>>>(edges);
    zero_kernel<<<gN, T>>>();
    convert_edges_kernel<<<gE, T>>>(edges);
    dinv_kernel<<<gN, T>>>();
    scan_kernel<<<1, 1024>>>();
    csr_fill_kernel<<<gE, T>>>();

    // layer 1: 128 -> 64  (x is raw input, no relu on load)
    gemm64_kernel<128, false><<<gRow, T>>>(x, W1, h, NN);
    gather64_kernel<<<gN16, T>>>(h, b1, a);

    // layer 2: 64 -> 64   (relu of layer-1 output fused into gemm load)
    gemm64_kernel<64, true><<<gRow, T>>>(a, W2, h, NN);
    gather64_kernel<<<gN16, T>>>(h, b2, a);

    // layer 3: 64 -> 7    (relu fused into gemm7 load), straight into d_out
    gemm7_kernel<<<gRow, T>>>(a, W3, h, NN);
    gather7_kernel<<<gN8, T>>>(h, b3, out);
    (void)in_sizes; (void)n_in; (void)out_size;
}

// round 9
// speedup vs baseline: 1.4603x; 1.4603x over previous
#include <cuda_runtime.h>
#include <cuda_bf16.h>
#include <cstdint>

#define NN 100000
#define NE 800000
#define NB ((NN + 1023) / 1024)   /* 98 scan blocks */
// dims: 128 -> 64 -> 64 -> 7

// ---------------- scratch (device globals; no allocation allowed) ----------
__device__ __align__(256) float g_h[NN * 64];   // GEMM output of current layer
__device__ __align__(256) float g_a[NN * 64];   // aggregated output / next input
__device__ float g_dinv[NN];
__device__ int   g_deg[NN];
__device__ int   g_cursor[NN];
__device__ int   g_rowptr[NN + 1];
__device__ int   g_bsum[NB];
__device__ int   g_boff[NB];
__device__ int   g_src[NE];
__device__ int   g_dst[NE];
__device__ __align__(256) int2 g_csr[NE];       // {src, coef as float bits}
__device__ int   g_is64;

// ---------------- helpers --------------------------------------------------
__device__ __forceinline__ void ffma2(unsigned long long& acc,
                                      unsigned long long a,
                                      unsigned long long b) {
    asm("fma.rn.f32x2 %0, %1, %2, %0;" : "+l"(acc) : "l"(a), "l"(b));
}

__device__ __forceinline__ unsigned long long dup2(float v) {
    unsigned int u = __float_as_uint(v);
    return ((unsigned long long)u << 32) | (unsigned long long)u;
}

__device__ __forceinline__ float lo32(unsigned long long v) {
    return __uint_as_float((unsigned int)(v & 0xffffffffull));
}
__device__ __forceinline__ float hi32(unsigned long long v) {
    return __uint_as_float((unsigned int)(v >> 32));
}

// ---------------- preprocessing --------------------------------------------
// Fused: zero deg/cursor (all blocks) + edge dtype detection (block 0).
// Detection: read the first 1024 int64 interpretations; if every one is a
// plausible node id the buffer really is int64 (int32 data reinterpreted as
// int64 pairs nearly always produces huge/invalid values).
__global__ void pre_kernel(const void* edges) {
    int gid = blockIdx.x * blockDim.x + threadIdx.x;
    if (gid < NN) { g_deg[gid] = 0; g_cursor[gid] = 0; }
    if (blockIdx.x == 0) {
        const long long* p = (const long long*)edges;
        int t = threadIdx.x;               // 256 threads x 4 reads = 1024 int64
        int ok = 1;
        #pragma unroll
        for (int j = 0; j < 4; j++) {
            long long v = p[t * 4 + j];
            ok &= (v >= 0 && v < NN);
        }
        int all = __syncthreads_and(ok);
        if (t == 0) g_is64 = all;
    }
}

__global__ void convert_edges_kernel(const void* edges) {
    int e = blockIdx.x * blockDim.x + threadIdx.x;
    if (e >= NE) return;
    int s, d;
    if (g_is64) {
        const long long* p = (const long long*)edges;
        s = (int)p[e];
        d = (int)p[NE + e];
    } else {
        const int* p = (const int*)edges;
        s = p[e];
        d = p[NE + e];
    }
    g_src[e] = s;
    g_dst[e] = d;
    atomicAdd(&g_deg[d], 1);
}

// scan phase 1: per-block sums of deg (grid NB x 1024); fuses dinv compute.
__global__ void __launch_bounds__(1024) scan1_kernel() {
    __shared__ int s[1024];
    int b = blockIdx.x, t = threadIdx.x;
    int i = b * 1024 + t;
    int d = 0;
    if (i < NN) {
        d = g_deg[i];
        g_dinv[i] = rsqrtf((float)d + 1.0f);
    }
    s[t] = d;
    __syncthreads();
    #pragma unroll
    for (int off = 512; off > 0; off >>= 1) {
        if (t < off) s[t] += s[t + off];
        __syncthreads();
    }
    if (t == 0) g_bsum[b] = s[0];
}

// scan phase 2: serial exclusive scan of the NB block sums (tiny).
__global__ void scan2_kernel() {
    int run = 0;
    for (int j = 0; j < NB; j++) { g_boff[j] = run; run += g_bsum[j]; }
    g_rowptr[NN] = NE;
}

// scan phase 3: block-local exclusive scan + block offset -> rowptr.
__global__ void __launch_bounds__(1024) scan3_kernel() {
    __shared__ int s[1024];
    int b = blockIdx.x, t = threadIdx.x;
    int i = b * 1024 + t;
    int d = (i < NN) ? g_deg[i] : 0;
    s[t] = d;
    __syncthreads();
    // Hillis-Steele inclusive scan over 1024
    #pragma unroll
    for (int off = 1; off < 1024; off <<= 1) {
        int v = (t >= off) ? s[t - off] : 0;
        __syncthreads();
        s[t] += v;
        __syncthreads();
    }
    if (i < NN) g_rowptr[i] = g_boff[b] + s[t] - d;   // exclusive prefix
}

// Bucket edges by destination; pack {src, coef} per slot.
__global__ void csr_fill_kernel() {
    int e = blockIdx.x * blockDim.x + threadIdx.x;
    if (e >= NE) return;
    int s = g_src[e];
    int d = g_dst[e];
    int pos = atomicAdd(&g_cursor[d], 1);
    int slot = g_rowptr[d] + pos;
    float coef = g_dinv[s] * g_dinv[d];
    g_csr[slot] = make_int2(s, __float_as_int(coef));
}

// ---------------- GEMM: [nrows,FIN] @ [FIN,64] -> [nrows,64] ---------------
// 64x64 output tile per 256-thread block, K chunked by 32.
// Inner loop uses packed fma.rn.f32x2: X tile stored duplicated ({v,v} u64)
// so the broadcast A operand is a single LDS.64; B column pairs come directly
// from the W tile bytes as ulonglong2 (one LDS.128).
// RELU applies relu to input X at load time (fused previous-layer activation).
template <int FIN, bool RELU>
__global__ void __launch_bounds__(256) gemm64_kernel(
    const float* __restrict__ X, const float* __restrict__ W,
    float* __restrict__ H, int nrows)
{
    constexpr int KC = 32;
    __shared__ unsigned long long sxp[64 * KC];   // 16KB: duplicated X tile
    __shared__ float4 sw4[KC * 16];               // 8KB : W tile (KC x 64)
    const ulonglong2* swp = reinterpret_cast<const ulonglong2*>(sw4);

    const int t  = threadIdx.x;
    const int tr = t >> 4;          // 0..15 -> rows tr*4..tr*4+3
    const int tc = t & 15;          // 0..15 -> cols tc*4..tc*4+3
    const int row0 = blockIdx.x * 64;

    unsigned long long acc[4][2];
    #pragma unroll
    for (int I = 0; I < 4; I++) { acc[I][0] = 0ull; acc[I][1] = 0ull; }

    for (int kc = 0; kc < FIN; kc += KC) {
        // load X tile: 64 rows x 8 float4 (coalesced, guarded), duplicated store
        #pragma unroll
        for (int idx = t; idx < 64 * 8; idx += 256) {
            int r = idx >> 3, kq = idx & 7;
            float4 v = make_float4(0.f, 0.f, 0.f, 0.f);
            int row = row0 + r;
            if (row < nrows)
                v = ((const float4*)X)[row * (FIN / 4) + (kc >> 2) + kq];
            if (RELU) {
                v.x = fmaxf(v.x, 0.f); v.y = fmaxf(v.y, 0.f);
                v.z = fmaxf(v.z, 0.f); v.w = fmaxf(v.w, 0.f);
            }
            unsigned long long* dst = &sxp[r * KC + kq * 4];
            dst[0] = dup2(v.x); dst[1] = dup2(v.y);
            dst[2] = dup2(v.z); dst[3] = dup2(v.w);
        }
        // load W tile: KC x 16 float4 (coalesced)
        #pragma unroll
        for (int idx = t; idx < KC * 16; idx += 256) {
            sw4[idx] = ((const float4*)W)[(kc + (idx >> 4)) * 16 + (idx & 15)];
        }
        __syncthreads();

        #pragma unroll
        for (int k = 0; k < KC; k++) {
            ulonglong2 b = swp[k * 16 + tc];          // cols tc*4..tc*4+3
            #pragma unroll
            for (int I = 0; I < 4; I++) {
                unsigned long long a = sxp[(tr * 4 + I) * KC + k];  // {v,v}
                ffma2(acc[I][0], a, b.x);
                ffma2(acc[I][1], a, b.y);
            }
        }
        __syncthreads();
    }

    #pragma unroll
    for (int I = 0; I < 4; I++) {
        int row = row0 + tr * 4 + I;
        if (row < nrows) {
            float4 o;
            o.x = lo32(acc[I][0]); o.y = hi32(acc[I][0]);
            o.z = lo32(acc[I][1]); o.w = hi32(acc[I][1]);
            ((float4*)H)[row * 16 + tc] = o;
        }
    }
}

// ---------------- GEMM: [nrows,64] @ [64,7] -> [nrows,7] -------------------
// Applies relu to X at load (input is layer-2 pre-relu aggregation output).
__global__ void __launch_bounds__(256) gemm7_kernel(
    const float* __restrict__ X, const float* __restrict__ W,
    float* __restrict__ H, int nrows)
{
    __shared__ float sx[64 * 65];
    __shared__ float sw[64 * 7];
    int t = threadIdx.x;
    int row0 = blockIdx.x * 64;

    for (int idx = t; idx < 64 * 16; idx += 256) {
        int r = idx >> 4, kq = idx & 15;
        float4 v = make_float4(0.f, 0.f, 0.f, 0.f);
        int row = row0 + r;
        if (row < nrows) v = ((const float4*)X)[row * 16 + kq];
        float* dst = &sx[r * 65 + kq * 4];
        dst[0] = fmaxf(v.x, 0.f); dst[1] = fmaxf(v.y, 0.f);
        dst[2] = fmaxf(v.z, 0.f); dst[3] = fmaxf(v.w, 0.f);
    }
    // grid-stride: 448 > 256 threads
    for (int idx = t; idx < 64 * 7; idx += 256) sw[idx] = W[idx];
    __syncthreads();

    for (int o = t; o < 64 * 7; o += 256) {
        int r = o / 7, c = o % 7;
        float acc = 0.f;
        #pragma unroll 8
        for (int k = 0; k < 64; k++)
            acc += sx[r * 65 + k] * sw[k * 7 + c];
        int row = row0 + r;
        if (row < nrows) H[row * 7 + c] = acc;
    }
}

// ---------------- aggregation (CSR gather), F = 64 -------------------------
// out[i] = sum_{e in in(i)} coef[e]*h[src[e]] + h[i]*dinv[i]^2 + bias
// 16 threads per node (one float4 feature chunk each).
// Edge loop manually unrolled x2: both csr loads then both H loads issue
// back-to-back -> MLP 2 on the dependent index->data chain.
__global__ void __launch_bounds__(256) gather64_kernel(
    const float* __restrict__ H, const float* __restrict__ B,
    float* __restrict__ OUT)
{
    int gid = blockIdx.x * blockDim.x + threadIdx.x;   // NN*16 threads
    if (gid >= NN * 16) return;
    int i = gid >> 4, q = gid & 15;
    int beg = g_rowptr[i];
    int end = g_rowptr[i + 1];
    float s = g_dinv[i];
    float c = s * s;
    float4 v = ((const float4*)H)[i * 16 + q];
    float4 b = ((const float4*)B)[q];
    float4 acc;
    acc.x = v.x * c + b.x; acc.y = v.y * c + b.y;
    acc.z = v.z * c + b.z; acc.w = v.w * c + b.w;
    int e = beg;
    for (; e + 2 <= end; e += 2) {
        int2  sc0 = g_csr[e];
        int2  sc1 = g_csr[e + 1];
        float co0 = __int_as_float(sc0.y);
        float co1 = __int_as_float(sc1.y);
        float4 h0 = ((const float4*)H)[sc0.x * 16 + q];
        float4 h1 = ((const float4*)H)[sc1.x * 16 + q];
        acc.x += co0 * h0.x; acc.y += co0 * h0.y;
        acc.z += co0 * h0.z; acc.w += co0 * h0.w;
        acc.x += co1 * h1.x; acc.y += co1 * h1.y;
        acc.z += co1 * h1.z; acc.w += co1 * h1.w;
    }
    if (e < end) {
        int2  sc  = g_csr[e];
        float co  = __int_as_float(sc.y);
        float4 hv = ((const float4*)H)[sc.x * 16 + q];
        acc.x += co * hv.x; acc.y += co * hv.y;
        acc.z += co * hv.z; acc.w += co * hv.w;
    }
    ((float4*)OUT)[i * 16 + q] = acc;
}

// ---------------- aggregation (CSR gather), F = 7 --------------------------
__global__ void __launch_bounds__(256) gather7_kernel(
    const float* __restrict__ H, const float* __restrict__ B,
    float* __restrict__ OUT)
{
    int gid = blockIdx.x * blockDim.x + threadIdx.x;   // NN*8 threads
    if (gid >= NN * 8) return;
    int i = gid >> 3, c = gid & 7;
    if (c >= 7) return;
    int beg = g_rowptr[i];
    int end = g_rowptr[i + 1];
    float s = g_dinv[i];
    float acc = H[i * 7 + c] * (s * s) + B[c];
    for (int e = beg; e < end; e++) {
        int2  sc = g_csr[e];
        float co = __int_as_float(sc.y);
        acc += co * H[sc.x * 7 + c];
    }
    OUT[i * 7 + c] = acc;
}

// ---------------- launch ---------------------------------------------------
extern "C" void kernel_launch(void* const* d_in, const int* in_sizes, int n_in,
                              void* d_out, int out_size)
{
    const float* x     = (const float*)d_in[0];
    const void*  edges = d_in[1];
    const float* W1    = (const float*)d_in[2];
    const float* b1    = (const float*)d_in[3];
    const float* W2    = (const float*)d_in[4];
    const float* b2    = (const float*)d_in[5];
    const float* W3    = (const float*)d_in[6];
    const float* b3    = (const float*)d_in[7];
    float* out = (float*)d_out;

    float* h = nullptr; float* a = nullptr;
    cudaGetSymbolAddress((void**)&h, g_h);
    cudaGetSymbolAddress((void**)&a, g_a);

    const int T = 256;
    const int gN   = (NN + T - 1) / T;          // 391
    const int gE   = (NE + T - 1) / T;          // 3125
    const int gN16 = (NN * 16 + T - 1) / T;     // 6250
    const int gN8  = (NN * 8 + T - 1) / T;      // 3125
    const int gRow = (NN + 63) / 64;            // 1563

    // preprocessing: zero+detect, edges->int32+degree, parallel scan (+dinv),
    // CSR fill (+packed coef)
    pre_kernel<<<gN, T>>>(edges);
    convert_edges_kernel<<<gE, T>>>(edges);
    scan1_kernel<<<NB, 1024>>>();
    scan2_kernel<<<1, 1>>>();
    scan3_kernel<<<NB, 1024>>>();
    csr_fill_kernel<<<gE, T>>>();

    // layer 1: 128 -> 64  (x is raw input, no relu on load)
    gemm64_kernel<128, false><<<gRow, T>>>(x, W1, h, NN);
    gather64_kernel<<<gN16, T>>>(h, b1, a);

    // layer 2: 64 -> 64   (relu of layer-1 output fused into gemm load)
    gemm64_kernel<64, true><<<gRow, T>>>(a, W2, h, NN);
    gather64_kernel<<<gN16, T>>>(h, b2, a);

    // layer 3: 64 -> 7    (relu fused into gemm7 load), straight into d_out
    gemm7_kernel<<<gRow, T>>>(a, W3, h, NN);
    gather7_kernel<<<gN8, T>>>(h, b3, out);
    (void)in_sizes; (void)n_in; (void)out_size;
}